// round 15
// baseline (speedup 1.0000x reference)
#include <cuda_runtime.h>
#include <math.h>

// Shapes (hardcoded per reference)
#define V  32
#define B  128
#define P  256
#define J  75
#define S2 25
#define F1 500   // fc1 out
#define F2 200   // fc2 out
#define KX 800   // V*S2

// Scratch (device globals). k-major activations: coalesced across batch.
__device__ float g_z [V*B*J];                        // SLayer output
__device__ __align__(16) float g_xT[KX*B];           // concat acts, [k][b]
__device__ __align__(16) float g_y1[F1*B];           // fc1 post-BN, [f][b]

__device__ __forceinline__ float warpSum(float v) {
    #pragma unroll
    for (int o = 16; o > 0; o >>= 1) v += __shfl_down_sync(0xffffffffu, v, o);
    return v;
}

// ---------------------------------------------------------------------------
// Kernel 1: transform + SLayer. One block per (v, b-pair). blockDim = 160.
// (59.9us build version, verbatim: float2 points)
__global__ void k_slayer(const float* __restrict__ births, const float* __restrict__ lifetimes,
                         const int* __restrict__ mask, const float* __restrict__ centers,
                         const float* __restrict__ sharpness) {
    int blk = blockIdx.x;           // V * B/2 = 2048
    int v   = blk >> 6;
    int b0  = (blk & 63) << 1;
    __shared__ float2 sq[2][P];
    __shared__ int scnt[2];
    int tid = threadIdx.x;

    if (tid < 64) {
        int w = tid >> 5, lane = tid & 31;
        int base = (v*B + b0 + w) * P;
        int cnt = 0;
        #pragma unroll
        for (int c = 0; c < P/32; ++c) {
            int p = c*32 + lane;
            int mv = mask[base + p];
            float bb = births[base + p], ll = lifetimes[base + p];
            float dd = bb + ll + 0.01f;
            const float inv = 0.70710678118654752440f;
            float x = (bb + dd) * inv;
            float y = (dd - bb) * inv;
            if (y <= 0.1f) y = __logf(y * 10.0f) * 0.1f + 0.1f;
            unsigned bal = __ballot_sync(0xffffffffu, mv != 0);
            if (mv) {
                int pos = cnt + __popc(bal & ((1u << lane) - 1u));
                sq[w][pos] = make_float2(x, y);
            }
            cnt += __popc(bal);
        }
        if (lane == 0) scnt[w] = cnt;
    }
    __syncthreads();

    if (tid < 2*J) {
        int w = (tid >= J);
        int j = tid - w*J;
        int n = scnt[w];
        int cj = (v*J + j) * 2;
        float cx = centers[cj], cy = centers[cj+1];
        float sx = sharpness[cj];   sx *= sx;
        float sy = sharpness[cj+1]; sy *= sy;
        float acc = 0.f;
        const float2* q = sq[w];
        for (int p = 0; p < n; ++p) {
            float2 pt = q[p];
            float dx = pt.x - cx;
            float dy = pt.y - cy;
            float d2 = fmaf(sx*dx, dx, sy*dy*dy);
            acc += __expf(-d2);
        }
        g_z[(v*B + b0 + w)*J + j] = acc;
    }
}

// ---------------------------------------------------------------------------
// Kernel 2: prew + neighbor stack + stage_1(max) + l1 + BN1 + l2 + ReLU.
// One block per v. blockDim = 512. (59.9us build version, verbatim)
__global__ void k_mid(const float* __restrict__ w1, const float* __restrict__ w2,
                      const float* __restrict__ l1_w, const float* __restrict__ l1_b,
                      const float* __restrict__ bn1_g, const float* __restrict__ bn1_b,
                      const float* __restrict__ l2_w, const float* __restrict__ l2_b) {
    int v = blockIdx.x;
    __shared__ float sW[24];
    __shared__ float hh[64*J];
    __shared__ float su[B*S2];
    __shared__ float sl1[S2*J];
    __shared__ float sl2[S2*S2];
    __shared__ float smean[S2], sscale[S2], sbeta[S2], sb1[S2], sb2[S2];
    int tid = threadIdx.x;

    if (tid < 24) {
        int g = tid/3, c = tid%3;
        float acc = 0.f;
        #pragma unroll 8
        for (int f = 0; f < 32; ++f)
            acc = fmaf(w2[(v*8+g)*32 + f], w1[(v*32+f)*3 + c], acc);
        sW[tid] = acc;
    }
    for (int i = tid; i < S2*J;  i += 512) sl1[i] = l1_w[v*S2*J  + i];
    for (int i = tid; i < S2*S2; i += 512) sl2[i] = l2_w[v*S2*S2 + i];
    if (tid < S2) { sb1[tid] = l1_b[v*S2+tid]; sb2[tid] = l2_b[v*S2+tid]; sbeta[tid] = bn1_b[v*S2+tid]; }
    __syncthreads();

    int vm = (v + V - 1) & (V - 1), vp = (v + 1) & (V - 1);
    for (int half = 0; half < 2; ++half) {
        int bb0 = half * 64;
        for (int i = tid; i < 64*J; i += 512) {
            int bl = i / J, j = i % J, b = bb0 + bl;
            float z0 = g_z[(vm*B + b)*J + j];
            float z1 = g_z[(v *B + b)*J + j];
            float z2 = g_z[(vp*B + b)*J + j];
            float m = -INFINITY;
            #pragma unroll
            for (int g = 0; g < 8; ++g) {
                float s = fmaf(sW[g*3+2], z2, fmaf(sW[g*3+1], z1, sW[g*3]*z0));
                m = fmaxf(m, s);
            }
            hh[i] = m;
        }
        __syncthreads();
        for (int i = tid; i < S2*64; i += 512) {
            int o = i / 64, bl = i % 64;
            float acc = sb1[o];
            const float* hr = &hh[bl*J];
            const float* wr = &sl1[o*J];
            #pragma unroll 5
            for (int j = 0; j < J; ++j) acc = fmaf(hr[j], wr[j], acc);
            su[(bb0 + bl)*S2 + o] = acc;
        }
        __syncthreads();
    }

    int warp = tid >> 5, lane = tid & 31;
    for (int o = warp; o < S2; o += 16) {
        float s = 0.f;
        #pragma unroll
        for (int b = lane; b < B; b += 32) s += su[b*S2 + o];
        s = warpSum(s);
        s = __shfl_sync(0xffffffffu, s, 0);
        float mean = s * (1.f / B);
        float vv = 0.f;
        #pragma unroll
        for (int b = lane; b < B; b += 32) { float d = su[b*S2 + o] - mean; vv = fmaf(d, d, vv); }
        vv = warpSum(vv);
        if (lane == 0) { smean[o] = mean; sscale[o] = bn1_g[v*S2+o] * rsqrtf(vv*(1.f/B) + 1e-5f); }
    }
    __syncthreads();

    for (int i = tid; i < B*S2; i += 512) {
        int o = i % S2;
        su[i] = (su[i] - smean[o]) * sscale[o] + sbeta[o];
    }
    __syncthreads();

    for (int i = tid; i < S2*B; i += 512) {
        int p = i / B, b = i % B;
        float acc = sb2[p];
        const float* ur = &su[b*S2];
        const float* wr = &sl2[p*S2];
        #pragma unroll
        for (int o = 0; o < S2; ++o) acc = fmaf(ur[o], wr[o], acc);
        g_xT[(v*S2 + p)*B + b] = fmaxf(acc, 0.f);
    }
}

// ---------------------------------------------------------------------------
// Kernel 3: fc1 (800->500) + BN2. FPB=4, grid=125, blockDim=1024 (32 warps).
// 32 k-slices of 25. part holds 16 slices; warps 16-31 add into w-16.
#define FPB 4
__global__ void __launch_bounds__(1024, 1)
k_fc1(const float* __restrict__ fc1_w, const float* __restrict__ fc1_b,
      const float* __restrict__ bn2_g, const float* __restrict__ bn2_b) {
    __shared__ float sw[FPB*KX];            // 12.8 KB
    __shared__ float part[16*FPB*B];        // 32 KB
    __shared__ float smean[FPB], sscale[FPB];
    int f0 = blockIdx.x * FPB;
    int tid = threadIdx.x;
    int w = tid >> 5, lane = tid & 31;

    for (int i = tid; i < FPB*KX; i += 1024) sw[i] = fc1_w[f0*KX + i];
    __syncthreads();

    float acc[FPB][4];
    #pragma unroll
    for (int ff = 0; ff < FPB; ++ff) {
        float bv = (w == 0) ? fc1_b[f0+ff] : 0.f;
        acc[ff][0] = bv; acc[ff][1] = bv; acc[ff][2] = bv; acc[ff][3] = bv;
    }
    const float4* x4 = reinterpret_cast<const float4*>(g_xT);  // [k][b/4]
    int k0 = w * 25;                       // 32 slices x 25 k
    #pragma unroll 5
    for (int k = k0; k < k0 + 25; ++k) {
        float4 xv = x4[k*32 + lane];
        #pragma unroll
        for (int ff = 0; ff < FPB; ++ff) {
            float wv = sw[ff*KX + k];
            acc[ff][0] = fmaf(wv, xv.x, acc[ff][0]);
            acc[ff][1] = fmaf(wv, xv.y, acc[ff][1]);
            acc[ff][2] = fmaf(wv, xv.z, acc[ff][2]);
            acc[ff][3] = fmaf(wv, xv.w, acc[ff][3]);
        }
    }
    if (w < 16) {
        #pragma unroll
        for (int ff = 0; ff < FPB; ++ff)
            #pragma unroll
            for (int u = 0; u < 4; ++u)
                part[(w*FPB + ff)*B + 4*lane + u] = acc[ff][u];
    }
    __syncthreads();
    if (w >= 16) {                         // one warp per slot: race-free
        #pragma unroll
        for (int ff = 0; ff < FPB; ++ff)
            #pragma unroll
            for (int u = 0; u < 4; ++u)
                part[((w-16)*FPB + ff)*B + 4*lane + u] += acc[ff][u];
    }
    __syncthreads();
    // serial deterministic combine over the 16 merged slices
    for (int i = tid; i < FPB*B; i += 1024) {
        float s = part[i];
        #pragma unroll
        for (int ks = 1; ks < 16; ++ks) s += part[ks*FPB*B + i];
        part[i] = s;
    }
    __syncthreads();

    if (w < FPB) {
        float s = 0.f;
        #pragma unroll
        for (int b = lane; b < B; b += 32) s += part[w*B + b];
        s = warpSum(s);
        s = __shfl_sync(0xffffffffu, s, 0);
        float mean = s * (1.f / B);
        float vv = 0.f;
        #pragma unroll
        for (int b = lane; b < B; b += 32) { float d = part[w*B + b] - mean; vv = fmaf(d, d, vv); }
        vv = warpSum(vv);
        if (lane == 0) { smean[w] = mean; sscale[w] = bn2_g[f0+w] * rsqrtf(vv*(1.f/B) + 1e-5f); }
    }
    __syncthreads();

    for (int i = tid; i < FPB*B; i += 1024) {
        int ff = i / B, b = i % B;
        g_y1[(f0+ff)*B + b] = (part[i] - smean[ff]) * sscale[ff] + bn2_b[f0+ff];
    }
}

// ---------------------------------------------------------------------------
// Kernel 4: fc2 (500->200). OPB=2, grid=100, blockDim=1024 (32 warps).
// 32 k-slices of ~16. part holds 16 slices; warps 16-31 add into w-16.
#define OPB 2
__global__ void __launch_bounds__(1024, 1)
k_fc2(const float* __restrict__ fc2_w, const float* __restrict__ fc2_b,
      float* __restrict__ out) {
    __shared__ float sw[OPB*F1];            // 4 KB
    __shared__ float part[16*OPB*B];        // 16 KB
    int o0 = blockIdx.x * OPB;
    int tid = threadIdx.x;
    int w = tid >> 5, lane = tid & 31;

    for (int i = tid; i < OPB*F1; i += 1024) sw[i] = fc2_w[o0*F1 + i];
    __syncthreads();

    float a0[4], a1[4];
    {
        float b0 = (w == 0) ? fc2_b[o0]   : 0.f;
        float b1 = (w == 0) ? fc2_b[o0+1] : 0.f;
        a0[0]=b0; a0[1]=b0; a0[2]=b0; a0[3]=b0;
        a1[0]=b1; a1[1]=b1; a1[2]=b1; a1[3]=b1;
    }
    const float4* y4 = reinterpret_cast<const float4*>(g_y1);  // [f][b/4]
    int fs = (w * F1) / 32, fe = ((w + 1) * F1) / 32;
    #pragma unroll 4
    for (int f = fs; f < fe; ++f) {
        float4 yv = y4[f*32 + lane];
        float w0 = sw[f], w1 = sw[F1 + f];
        a0[0] = fmaf(w0, yv.x, a0[0]); a1[0] = fmaf(w1, yv.x, a1[0]);
        a0[1] = fmaf(w0, yv.y, a0[1]); a1[1] = fmaf(w1, yv.y, a1[1]);
        a0[2] = fmaf(w0, yv.z, a0[2]); a1[2] = fmaf(w1, yv.z, a1[2]);
        a0[3] = fmaf(w0, yv.w, a0[3]); a1[3] = fmaf(w1, yv.w, a1[3]);
    }
    if (w < 16) {
        #pragma unroll
        for (int u = 0; u < 4; ++u) {
            part[(w*OPB + 0)*B + 4*lane + u] = a0[u];
            part[(w*OPB + 1)*B + 4*lane + u] = a1[u];
        }
    }
    __syncthreads();
    if (w >= 16) {
        #pragma unroll
        for (int u = 0; u < 4; ++u) {
            part[((w-16)*OPB + 0)*B + 4*lane + u] += a0[u];
            part[((w-16)*OPB + 1)*B + 4*lane + u] += a1[u];
        }
    }
    __syncthreads();
    for (int i = tid; i < OPB*B; i += 1024) {
        float s = part[i];
        #pragma unroll
        for (int ks = 1; ks < 16; ++ks) s += part[ks*OPB*B + i];
        int oo = i / B, b = i % B;
        out[b*F2 + o0 + oo] = s;
    }
}

// ---------------------------------------------------------------------------
extern "C" void kernel_launch(void* const* d_in, const int* in_sizes, int n_in,
                              void* d_out, int out_size) {
    const float* births    = (const float*)d_in[0];
    const float* lifetimes = (const float*)d_in[1];
    const int*   mask      = (const int*)  d_in[2];
    const float* centers   = (const float*)d_in[3];
    const float* sharpness = (const float*)d_in[4];
    const float* w1        = (const float*)d_in[5];
    const float* w2        = (const float*)d_in[6];
    const float* l1_w      = (const float*)d_in[7];
    const float* l1_b      = (const float*)d_in[8];
    const float* bn1_g     = (const float*)d_in[9];
    const float* bn1_b     = (const float*)d_in[10];
    const float* l2_w      = (const float*)d_in[11];
    const float* l2_b      = (const float*)d_in[12];
    const float* fc1_w     = (const float*)d_in[13];
    const float* fc1_b     = (const float*)d_in[14];
    const float* bn2_g     = (const float*)d_in[15];
    const float* bn2_b     = (const float*)d_in[16];
    const float* fc2_w     = (const float*)d_in[17];
    const float* fc2_b     = (const float*)d_in[18];
    float* out = (float*)d_out;

    k_slayer<<<V*B/2, 160>>>(births, lifetimes, mask, centers, sharpness);
    k_mid   <<<V, 512>>>(w1, w2, l1_w, l1_b, bn1_g, bn1_b, l2_w, l2_b);
    k_fc1   <<<F1/FPB, 1024>>>(fc1_w, fc1_b, bn2_g, bn2_b);
    k_fc2   <<<F2/OPB, 1024>>>(fc2_w, fc2_b, out);
}

// round 16
// speedup vs baseline: 1.0734x; 1.0734x over previous
#include <cuda_runtime.h>
#include <math.h>

// Shapes (hardcoded per reference)
#define V  32
#define B  128
#define P  256
#define J  75
#define S2 25
#define F1 500   // fc1 out
#define F2 200   // fc2 out
#define KX 800   // V*S2

// Scratch (device globals). k-major activations: coalesced across batch.
__device__ float g_z [V*B*J];                        // SLayer output
__device__ float g_u1[V*B*S2];                       // stage_2 pre-BN
__device__ __align__(16) float g_xT[KX*B];           // concat acts, [k][b]
__device__ __align__(16) float g_y1[F1*B];           // fc1 post-BN, [f][b]

__device__ __forceinline__ float warpSum(float v) {
    #pragma unroll
    for (int o = 16; o > 0; o >>= 1) v += __shfl_down_sync(0xffffffffu, v, o);
    return v;
}

// ---------------------------------------------------------------------------
// Kernel 1: transform + SLayer. One block per (v, b-pair). blockDim = 160.
// (59.9us build version, verbatim: float2 points)
__global__ void k_slayer(const float* __restrict__ births, const float* __restrict__ lifetimes,
                         const int* __restrict__ mask, const float* __restrict__ centers,
                         const float* __restrict__ sharpness) {
    int blk = blockIdx.x;           // V * B/2 = 2048
    int v   = blk >> 6;
    int b0  = (blk & 63) << 1;
    __shared__ float2 sq[2][P];
    __shared__ int scnt[2];
    int tid = threadIdx.x;

    if (tid < 64) {
        int w = tid >> 5, lane = tid & 31;
        int base = (v*B + b0 + w) * P;
        int cnt = 0;
        #pragma unroll
        for (int c = 0; c < P/32; ++c) {
            int p = c*32 + lane;
            int mv = mask[base + p];
            float bb = births[base + p], ll = lifetimes[base + p];
            float dd = bb + ll + 0.01f;
            const float inv = 0.70710678118654752440f;
            float x = (bb + dd) * inv;
            float y = (dd - bb) * inv;
            if (y <= 0.1f) y = __logf(y * 10.0f) * 0.1f + 0.1f;
            unsigned bal = __ballot_sync(0xffffffffu, mv != 0);
            if (mv) {
                int pos = cnt + __popc(bal & ((1u << lane) - 1u));
                sq[w][pos] = make_float2(x, y);
            }
            cnt += __popc(bal);
        }
        if (lane == 0) scnt[w] = cnt;
    }
    __syncthreads();

    if (tid < 2*J) {
        int w = (tid >= J);
        int j = tid - w*J;
        int n = scnt[w];
        int cj = (v*J + j) * 2;
        float cx = centers[cj], cy = centers[cj+1];
        float sx = sharpness[cj];   sx *= sx;
        float sy = sharpness[cj+1]; sy *= sy;
        float acc = 0.f;
        const float2* q = sq[w];
        for (int p = 0; p < n; ++p) {
            float2 pt = q[p];
            float dx = pt.x - cx;
            float dy = pt.y - cy;
            float d2 = fmaf(sx*dx, dx, sy*dy*dy);
            acc += __expf(-d2);
        }
        g_z[(v*B + b0 + w)*J + j] = acc;
    }
}

// ---------------------------------------------------------------------------
// Kernel 2a: prew + neighbor stack + stage_1(max) + l1 -> g_u1.
// grid = V*8 = 256 blocks (one per (v, 16-batch group)), blockDim = 256.
__global__ void k_h(const float* __restrict__ w1, const float* __restrict__ w2,
                    const float* __restrict__ l1_w, const float* __restrict__ l1_b) {
    int blk = blockIdx.x;
    int v  = blk >> 3;
    int b0 = (blk & 7) * 16;
    __shared__ float sW[24];
    __shared__ float sl1[S2*J];      // 7.5 KB
    __shared__ float sb1[S2];
    __shared__ float hh[16*J];       // 4.8 KB
    int tid = threadIdx.x;

    if (tid < 24) {                  // fused stage_1 weights: W = w2 @ w1
        int g = tid/3, c = tid%3;
        float acc = 0.f;
        #pragma unroll 8
        for (int f = 0; f < 32; ++f)
            acc = fmaf(w2[(v*8+g)*32 + f], w1[(v*32+f)*3 + c], acc);
        sW[tid] = acc;
    }
    for (int i = tid; i < S2*J; i += 256) sl1[i] = l1_w[v*S2*J + i];
    if (tid < S2) sb1[tid] = l1_b[v*S2 + tid];
    __syncthreads();

    int vm = (v + V - 1) & (V - 1), vp = (v + 1) & (V - 1);
    for (int i = tid; i < 16*J; i += 256) {
        int bl = i / J, j = i % J, b = b0 + bl;
        float z0 = g_z[(vm*B + b)*J + j];
        float z1 = g_z[(v *B + b)*J + j];
        float z2 = g_z[(vp*B + b)*J + j];
        float m = -INFINITY;
        #pragma unroll
        for (int g = 0; g < 8; ++g) {
            float s = fmaf(sW[g*3+2], z2, fmaf(sW[g*3+1], z1, sW[g*3]*z0));
            m = fmaxf(m, s);
        }
        hh[i] = m;
    }
    __syncthreads();

    for (int i = tid; i < 16*S2; i += 256) {
        int bl = i / S2, o = i % S2;
        float acc = sb1[o];
        const float* hr = &hh[bl*J];
        const float* wr = &sl1[o*J];
        #pragma unroll 5
        for (int j = 0; j < J; ++j) acc = fmaf(hr[j], wr[j], acc);
        g_u1[(v*B + b0 + bl)*S2 + o] = acc;
    }
}

// ---------------------------------------------------------------------------
// Kernel 2b: BN1 + l2 + ReLU, write k-major g_xT. One block per v, 256 thr.
__global__ void k_bn(const float* __restrict__ bn1_g, const float* __restrict__ bn1_b,
                     const float* __restrict__ l2_w, const float* __restrict__ l2_b) {
    int v = blockIdx.x;
    __shared__ float su[B*S2];       // 12.8 KB
    __shared__ float sl2[S2*S2];     // 2.5 KB
    __shared__ float smean[S2], sscale[S2], sbeta[S2], sb2[S2];
    int tid = threadIdx.x;

    for (int i = tid; i < B*S2; i += 256)  su[i] = g_u1[v*B*S2 + i];
    for (int i = tid; i < S2*S2; i += 256) sl2[i] = l2_w[v*S2*S2 + i];
    if (tid < S2) { sb2[tid] = l2_b[v*S2+tid]; sbeta[tid] = bn1_b[v*S2+tid]; }
    __syncthreads();

    int warp = tid >> 5, lane = tid & 31;
    for (int o = warp; o < S2; o += 8) {
        float s = 0.f;
        #pragma unroll
        for (int b = lane; b < B; b += 32) s += su[b*S2 + o];
        s = warpSum(s);
        s = __shfl_sync(0xffffffffu, s, 0);
        float mean = s * (1.f / B);
        float vv = 0.f;
        #pragma unroll
        for (int b = lane; b < B; b += 32) { float d = su[b*S2 + o] - mean; vv = fmaf(d, d, vv); }
        vv = warpSum(vv);
        if (lane == 0) { smean[o] = mean; sscale[o] = bn1_g[v*S2+o] * rsqrtf(vv*(1.f/B) + 1e-5f); }
    }
    __syncthreads();

    for (int i = tid; i < B*S2; i += 256) {
        int o = i % S2;
        su[i] = (su[i] - smean[o]) * sscale[o] + sbeta[o];
    }
    __syncthreads();

    for (int i = tid; i < S2*B; i += 256) {
        int p = i / B, b = i % B;
        float acc = sb2[p];
        const float* ur = &su[b*S2];
        const float* wr = &sl2[p*S2];
        #pragma unroll
        for (int o = 0; o < S2; ++o) acc = fmaf(ur[o], wr[o], acc);
        g_xT[(v*S2 + p)*B + b] = fmaxf(acc, 0.f);
    }
}

// ---------------------------------------------------------------------------
// Kernel 3: fc1 (800->500) + BN2. FPB=4, grid=125, blockDim=1024 (32 warps).
// (59.9us/R15 version, verbatim)
#define FPB 4
__global__ void __launch_bounds__(1024, 1)
k_fc1(const float* __restrict__ fc1_w, const float* __restrict__ fc1_b,
      const float* __restrict__ bn2_g, const float* __restrict__ bn2_b) {
    __shared__ float sw[FPB*KX];            // 12.8 KB
    __shared__ float part[16*FPB*B];        // 32 KB
    __shared__ float smean[FPB], sscale[FPB];
    int f0 = blockIdx.x * FPB;
    int tid = threadIdx.x;
    int w = tid >> 5, lane = tid & 31;

    for (int i = tid; i < FPB*KX; i += 1024) sw[i] = fc1_w[f0*KX + i];
    __syncthreads();

    float acc[FPB][4];
    #pragma unroll
    for (int ff = 0; ff < FPB; ++ff) {
        float bv = (w == 0) ? fc1_b[f0+ff] : 0.f;
        acc[ff][0] = bv; acc[ff][1] = bv; acc[ff][2] = bv; acc[ff][3] = bv;
    }
    const float4* x4 = reinterpret_cast<const float4*>(g_xT);  // [k][b/4]
    int k0 = w * 25;
    #pragma unroll 5
    for (int k = k0; k < k0 + 25; ++k) {
        float4 xv = x4[k*32 + lane];
        #pragma unroll
        for (int ff = 0; ff < FPB; ++ff) {
            float wv = sw[ff*KX + k];
            acc[ff][0] = fmaf(wv, xv.x, acc[ff][0]);
            acc[ff][1] = fmaf(wv, xv.y, acc[ff][1]);
            acc[ff][2] = fmaf(wv, xv.z, acc[ff][2]);
            acc[ff][3] = fmaf(wv, xv.w, acc[ff][3]);
        }
    }
    if (w < 16) {
        #pragma unroll
        for (int ff = 0; ff < FPB; ++ff)
            #pragma unroll
            for (int u = 0; u < 4; ++u)
                part[(w*FPB + ff)*B + 4*lane + u] = acc[ff][u];
    }
    __syncthreads();
    if (w >= 16) {
        #pragma unroll
        for (int ff = 0; ff < FPB; ++ff)
            #pragma unroll
            for (int u = 0; u < 4; ++u)
                part[((w-16)*FPB + ff)*B + 4*lane + u] += acc[ff][u];
    }
    __syncthreads();
    for (int i = tid; i < FPB*B; i += 1024) {
        float s = part[i];
        #pragma unroll
        for (int ks = 1; ks < 16; ++ks) s += part[ks*FPB*B + i];
        part[i] = s;
    }
    __syncthreads();

    if (w < FPB) {
        float s = 0.f;
        #pragma unroll
        for (int b = lane; b < B; b += 32) s += part[w*B + b];
        s = warpSum(s);
        s = __shfl_sync(0xffffffffu, s, 0);
        float mean = s * (1.f / B);
        float vv = 0.f;
        #pragma unroll
        for (int b = lane; b < B; b += 32) { float d = part[w*B + b] - mean; vv = fmaf(d, d, vv); }
        vv = warpSum(vv);
        if (lane == 0) { smean[w] = mean; sscale[w] = bn2_g[f0+w] * rsqrtf(vv*(1.f/B) + 1e-5f); }
    }
    __syncthreads();

    for (int i = tid; i < FPB*B; i += 1024) {
        int ff = i / B, b = i % B;
        g_y1[(f0+ff)*B + b] = (part[i] - smean[ff]) * sscale[ff] + bn2_b[f0+ff];
    }
}

// ---------------------------------------------------------------------------
// Kernel 4: fc2 (500->200). OPB=2, grid=100, blockDim=1024 (32 warps).
// (59.9us/R15 version, verbatim)
#define OPB 2
__global__ void __launch_bounds__(1024, 1)
k_fc2(const float* __restrict__ fc2_w, const float* __restrict__ fc2_b,
      float* __restrict__ out) {
    __shared__ float sw[OPB*F1];            // 4 KB
    __shared__ float part[16*OPB*B];        // 16 KB
    int o0 = blockIdx.x * OPB;
    int tid = threadIdx.x;
    int w = tid >> 5, lane = tid & 31;

    for (int i = tid; i < OPB*F1; i += 1024) sw[i] = fc2_w[o0*F1 + i];
    __syncthreads();

    float a0[4], a1[4];
    {
        float b0 = (w == 0) ? fc2_b[o0]   : 0.f;
        float b1 = (w == 0) ? fc2_b[o0+1] : 0.f;
        a0[0]=b0; a0[1]=b0; a0[2]=b0; a0[3]=b0;
        a1[0]=b1; a1[1]=b1; a1[2]=b1; a1[3]=b1;
    }
    const float4* y4 = reinterpret_cast<const float4*>(g_y1);  // [f][b/4]
    int fs = (w * F1) / 32, fe = ((w + 1) * F1) / 32;
    #pragma unroll 4
    for (int f = fs; f < fe; ++f) {
        float4 yv = y4[f*32 + lane];
        float w0 = sw[f], w1 = sw[F1 + f];
        a0[0] = fmaf(w0, yv.x, a0[0]); a1[0] = fmaf(w1, yv.x, a1[0]);
        a0[1] = fmaf(w0, yv.y, a0[1]); a1[1] = fmaf(w1, yv.y, a1[1]);
        a0[2] = fmaf(w0, yv.z, a0[2]); a1[2] = fmaf(w1, yv.z, a1[2]);
        a0[3] = fmaf(w0, yv.w, a0[3]); a1[3] = fmaf(w1, yv.w, a1[3]);
    }
    if (w < 16) {
        #pragma unroll
        for (int u = 0; u < 4; ++u) {
            part[(w*OPB + 0)*B + 4*lane + u] = a0[u];
            part[(w*OPB + 1)*B + 4*lane + u] = a1[u];
        }
    }
    __syncthreads();
    if (w >= 16) {
        #pragma unroll
        for (int u = 0; u < 4; ++u) {
            part[((w-16)*OPB + 0)*B + 4*lane + u] += a0[u];
            part[((w-16)*OPB + 1)*B + 4*lane + u] += a1[u];
        }
    }
    __syncthreads();
    for (int i = tid; i < OPB*B; i += 1024) {
        float s = part[i];
        #pragma unroll
        for (int ks = 1; ks < 16; ++ks) s += part[ks*OPB*B + i];
        int oo = i / B, b = i % B;
        out[b*F2 + o0 + oo] = s;
    }
}

// ---------------------------------------------------------------------------
extern "C" void kernel_launch(void* const* d_in, const int* in_sizes, int n_in,
                              void* d_out, int out_size) {
    const float* births    = (const float*)d_in[0];
    const float* lifetimes = (const float*)d_in[1];
    const int*   mask      = (const int*)  d_in[2];
    const float* centers   = (const float*)d_in[3];
    const float* sharpness = (const float*)d_in[4];
    const float* w1        = (const float*)d_in[5];
    const float* w2        = (const float*)d_in[6];
    const float* l1_w      = (const float*)d_in[7];
    const float* l1_b      = (const float*)d_in[8];
    const float* bn1_g     = (const float*)d_in[9];
    const float* bn1_b     = (const float*)d_in[10];
    const float* l2_w      = (const float*)d_in[11];
    const float* l2_b      = (const float*)d_in[12];
    const float* fc1_w     = (const float*)d_in[13];
    const float* fc1_b     = (const float*)d_in[14];
    const float* bn2_g     = (const float*)d_in[15];
    const float* bn2_b     = (const float*)d_in[16];
    const float* fc2_w     = (const float*)d_in[17];
    const float* fc2_b     = (const float*)d_in[18];
    float* out = (float*)d_out;

    k_slayer<<<V*B/2, 160>>>(births, lifetimes, mask, centers, sharpness);
    k_h     <<<V*8, 256>>>(w1, w2, l1_w, l1_b);
    k_bn    <<<V, 256>>>(bn1_g, bn1_b, l2_w, l2_b);
    k_fc1   <<<F1/FPB, 1024>>>(fc1_w, fc1_b, bn2_g, bn2_b);
    k_fc2   <<<F2/OPB, 1024>>>(fc2_w, fc2_b, out);
}

// round 17
// speedup vs baseline: 1.0753x; 1.0017x over previous
#include <cuda_runtime.h>
#include <math.h>

// Shapes (hardcoded per reference)
#define V  32
#define B  128
#define P  256
#define J  75
#define S2 25
#define F1 500   // fc1 out
#define F2 200   // fc2 out
#define KX 800   // V*S2

// Scratch (device globals). k-major activations: coalesced across batch.
__device__ float g_z [V*B*J];                        // SLayer output
__device__ float g_u1[V*B*S2];                       // stage_2 pre-BN
__device__ __align__(16) float g_xT[KX*B];           // concat acts, [k][b]
__device__ __align__(16) float g_y1[F1*B];           // fc1 post-BN, [f][b]

__device__ __forceinline__ float warpSum(float v) {
    #pragma unroll
    for (int o = 16; o > 0; o >>= 1) v += __shfl_down_sync(0xffffffffu, v, o);
    return v;
}

// ---------------------------------------------------------------------------
// Kernel 1: transform + SLayer. One block per (v, b-pair). blockDim = 160.
// (55.8us build version, verbatim)
__global__ void k_slayer(const float* __restrict__ births, const float* __restrict__ lifetimes,
                         const int* __restrict__ mask, const float* __restrict__ centers,
                         const float* __restrict__ sharpness) {
    int blk = blockIdx.x;           // V * B/2 = 2048
    int v   = blk >> 6;
    int b0  = (blk & 63) << 1;
    __shared__ float2 sq[2][P];
    __shared__ int scnt[2];
    int tid = threadIdx.x;

    if (tid < 64) {
        int w = tid >> 5, lane = tid & 31;
        int base = (v*B + b0 + w) * P;
        int cnt = 0;
        #pragma unroll
        for (int c = 0; c < P/32; ++c) {
            int p = c*32 + lane;
            int mv = mask[base + p];
            float bb = births[base + p], ll = lifetimes[base + p];
            float dd = bb + ll + 0.01f;
            const float inv = 0.70710678118654752440f;
            float x = (bb + dd) * inv;
            float y = (dd - bb) * inv;
            if (y <= 0.1f) y = __logf(y * 10.0f) * 0.1f + 0.1f;
            unsigned bal = __ballot_sync(0xffffffffu, mv != 0);
            if (mv) {
                int pos = cnt + __popc(bal & ((1u << lane) - 1u));
                sq[w][pos] = make_float2(x, y);
            }
            cnt += __popc(bal);
        }
        if (lane == 0) scnt[w] = cnt;
    }
    __syncthreads();

    if (tid < 2*J) {
        int w = (tid >= J);
        int j = tid - w*J;
        int n = scnt[w];
        int cj = (v*J + j) * 2;
        float cx = centers[cj], cy = centers[cj+1];
        float sx = sharpness[cj];   sx *= sx;
        float sy = sharpness[cj+1]; sy *= sy;
        float acc = 0.f;
        const float2* q = sq[w];
        for (int p = 0; p < n; ++p) {
            float2 pt = q[p];
            float dx = pt.x - cx;
            float dy = pt.y - cy;
            float d2 = fmaf(sx*dx, dx, sy*dy*dy);
            acc += __expf(-d2);
        }
        g_z[(v*B + b0 + w)*J + j] = acc;
    }
}

// ---------------------------------------------------------------------------
// Kernel 2a: prew + neighbor stack + stage_1(max) + l1 -> g_u1.
// grid = V*8 = 256 blocks, blockDim = 256. (55.8us build version, verbatim)
__global__ void k_h(const float* __restrict__ w1, const float* __restrict__ w2,
                    const float* __restrict__ l1_w, const float* __restrict__ l1_b) {
    int blk = blockIdx.x;
    int v  = blk >> 3;
    int b0 = (blk & 7) * 16;
    __shared__ float sW[24];
    __shared__ float sl1[S2*J];      // 7.5 KB
    __shared__ float sb1[S2];
    __shared__ float hh[16*J];       // 4.8 KB
    int tid = threadIdx.x;

    if (tid < 24) {
        int g = tid/3, c = tid%3;
        float acc = 0.f;
        #pragma unroll 8
        for (int f = 0; f < 32; ++f)
            acc = fmaf(w2[(v*8+g)*32 + f], w1[(v*32+f)*3 + c], acc);
        sW[tid] = acc;
    }
    for (int i = tid; i < S2*J; i += 256) sl1[i] = l1_w[v*S2*J + i];
    if (tid < S2) sb1[tid] = l1_b[v*S2 + tid];
    __syncthreads();

    int vm = (v + V - 1) & (V - 1), vp = (v + 1) & (V - 1);
    for (int i = tid; i < 16*J; i += 256) {
        int bl = i / J, j = i % J, b = b0 + bl;
        float z0 = g_z[(vm*B + b)*J + j];
        float z1 = g_z[(v *B + b)*J + j];
        float z2 = g_z[(vp*B + b)*J + j];
        float m = -INFINITY;
        #pragma unroll
        for (int g = 0; g < 8; ++g) {
            float s = fmaf(sW[g*3+2], z2, fmaf(sW[g*3+1], z1, sW[g*3]*z0));
            m = fmaxf(m, s);
        }
        hh[i] = m;
    }
    __syncthreads();

    for (int i = tid; i < 16*S2; i += 256) {
        int bl = i / S2, o = i % S2;
        float acc = sb1[o];
        const float* hr = &hh[bl*J];
        const float* wr = &sl1[o*J];
        #pragma unroll 5
        for (int j = 0; j < J; ++j) acc = fmaf(hr[j], wr[j], acc);
        g_u1[(v*B + b0 + bl)*S2 + o] = acc;
    }
}

// ---------------------------------------------------------------------------
// Kernel 2b: BN1 + l2 + ReLU, write k-major g_xT. One block per v, 512 thr.
__global__ void k_bn(const float* __restrict__ bn1_g, const float* __restrict__ bn1_b,
                     const float* __restrict__ l2_w, const float* __restrict__ l2_b) {
    int v = blockIdx.x;
    __shared__ float su[B*S2];       // 12.8 KB
    __shared__ float sl2[S2*S2];     // 2.5 KB
    __shared__ float smean[S2], sscale[S2], sbeta[S2], sb2[S2];
    int tid = threadIdx.x;

    for (int i = tid; i < B*S2; i += 512)  su[i] = g_u1[v*B*S2 + i];
    for (int i = tid; i < S2*S2; i += 512) sl2[i] = l2_w[v*S2*S2 + i];
    if (tid < S2) { sb2[tid] = l2_b[v*S2+tid]; sbeta[tid] = bn1_b[v*S2+tid]; }
    __syncthreads();

    int warp = tid >> 5, lane = tid & 31;
    for (int o = warp; o < S2; o += 16) {
        float s = 0.f;
        #pragma unroll
        for (int b = lane; b < B; b += 32) s += su[b*S2 + o];
        s = warpSum(s);
        s = __shfl_sync(0xffffffffu, s, 0);
        float mean = s * (1.f / B);
        float vv = 0.f;
        #pragma unroll
        for (int b = lane; b < B; b += 32) { float d = su[b*S2 + o] - mean; vv = fmaf(d, d, vv); }
        vv = warpSum(vv);
        if (lane == 0) { smean[o] = mean; sscale[o] = bn1_g[v*S2+o] * rsqrtf(vv*(1.f/B) + 1e-5f); }
    }
    __syncthreads();

    for (int i = tid; i < B*S2; i += 512) {
        int o = i % S2;
        su[i] = (su[i] - smean[o]) * sscale[o] + sbeta[o];
    }
    __syncthreads();

    for (int i = tid; i < S2*B; i += 512) {
        int p = i / B, b = i % B;
        float acc = sb2[p];
        const float* ur = &su[b*S2];
        const float* wr = &sl2[p*S2];
        #pragma unroll
        for (int o = 0; o < S2; ++o) acc = fmaf(ur[o], wr[o], acc);
        g_xT[(v*S2 + p)*B + b] = fmaxf(acc, 0.f);
    }
}

// ---------------------------------------------------------------------------
// Kernel 3: fc1 (800->500) + BN2. FPB=5, grid=100, blockDim=1024 (32 warps).
// 32 k-slices of 25; part holds 8 slices; warps 8..31 merge in 3 passes.
#define FPB 5
__global__ void __launch_bounds__(1024, 1)
k_fc1(const float* __restrict__ fc1_w, const float* __restrict__ fc1_b,
      const float* __restrict__ bn2_g, const float* __restrict__ bn2_b) {
    __shared__ float sw[FPB*KX];            // 16 KB
    __shared__ float part[8*FPB*B];         // 20 KB
    __shared__ float smean[FPB], sscale[FPB];
    int f0 = blockIdx.x * FPB;
    int tid = threadIdx.x;
    int w = tid >> 5, lane = tid & 31;

    for (int i = tid; i < FPB*KX; i += 1024) sw[i] = fc1_w[f0*KX + i];
    __syncthreads();

    float acc[FPB][4];
    #pragma unroll
    for (int ff = 0; ff < FPB; ++ff) {
        float bv = (w == 0) ? fc1_b[f0+ff] : 0.f;
        acc[ff][0] = bv; acc[ff][1] = bv; acc[ff][2] = bv; acc[ff][3] = bv;
    }
    const float4* x4 = reinterpret_cast<const float4*>(g_xT);  // [k][b/4]
    int k0 = w * 25;                        // 32 slices x 25 k
    #pragma unroll 5
    for (int k = k0; k < k0 + 25; ++k) {
        float4 xv = x4[k*32 + lane];
        #pragma unroll
        for (int ff = 0; ff < FPB; ++ff) {
            float wv = sw[ff*KX + k];
            acc[ff][0] = fmaf(wv, xv.x, acc[ff][0]);
            acc[ff][1] = fmaf(wv, xv.y, acc[ff][1]);
            acc[ff][2] = fmaf(wv, xv.z, acc[ff][2]);
            acc[ff][3] = fmaf(wv, xv.w, acc[ff][3]);
        }
    }
    // merge 32 slices into 8 part slots: 4 sequential race-free passes
    if (w < 8) {
        #pragma unroll
        for (int ff = 0; ff < FPB; ++ff)
            #pragma unroll
            for (int u = 0; u < 4; ++u)
                part[(w*FPB + ff)*B + 4*lane + u] = acc[ff][u];
    }
    __syncthreads();
    if (w >= 8 && w < 16) {
        #pragma unroll
        for (int ff = 0; ff < FPB; ++ff)
            #pragma unroll
            for (int u = 0; u < 4; ++u)
                part[((w-8)*FPB + ff)*B + 4*lane + u] += acc[ff][u];
    }
    __syncthreads();
    if (w >= 16 && w < 24) {
        #pragma unroll
        for (int ff = 0; ff < FPB; ++ff)
            #pragma unroll
            for (int u = 0; u < 4; ++u)
                part[((w-16)*FPB + ff)*B + 4*lane + u] += acc[ff][u];
    }
    __syncthreads();
    if (w >= 24) {
        #pragma unroll
        for (int ff = 0; ff < FPB; ++ff)
            #pragma unroll
            for (int u = 0; u < 4; ++u)
                part[((w-24)*FPB + ff)*B + 4*lane + u] += acc[ff][u];
    }
    __syncthreads();
    // serial deterministic combine over the 8 merged slices
    for (int i = tid; i < FPB*B; i += 1024) {
        float s = part[i];
        #pragma unroll
        for (int ks = 1; ks < 8; ++ks) s += part[ks*FPB*B + i];
        part[i] = s;
    }
    __syncthreads();

    if (w < FPB) {
        float s = 0.f;
        #pragma unroll
        for (int b = lane; b < B; b += 32) s += part[w*B + b];
        s = warpSum(s);
        s = __shfl_sync(0xffffffffu, s, 0);
        float mean = s * (1.f / B);
        float vv = 0.f;
        #pragma unroll
        for (int b = lane; b < B; b += 32) { float d = part[w*B + b] - mean; vv = fmaf(d, d, vv); }
        vv = warpSum(vv);
        if (lane == 0) { smean[w] = mean; sscale[w] = bn2_g[f0+w] * rsqrtf(vv*(1.f/B) + 1e-5f); }
    }
    __syncthreads();

    for (int i = tid; i < FPB*B; i += 1024) {
        int ff = i / B, b = i % B;
        g_y1[(f0+ff)*B + b] = (part[i] - smean[ff]) * sscale[ff] + bn2_b[f0+ff];
    }
}

// ---------------------------------------------------------------------------
// Kernel 4: fc2 (500->200). OPB=2, grid=100, blockDim=1024 (32 warps).
// (55.8us build version, verbatim)
#define OPB 2
__global__ void __launch_bounds__(1024, 1)
k_fc2(const float* __restrict__ fc2_w, const float* __restrict__ fc2_b,
      float* __restrict__ out) {
    __shared__ float sw[OPB*F1];            // 4 KB
    __shared__ float part[16*OPB*B];        // 16 KB
    int o0 = blockIdx.x * OPB;
    int tid = threadIdx.x;
    int w = tid >> 5, lane = tid & 31;

    for (int i = tid; i < OPB*F1; i += 1024) sw[i] = fc2_w[o0*F1 + i];
    __syncthreads();

    float a0[4], a1[4];
    {
        float b0 = (w == 0) ? fc2_b[o0]   : 0.f;
        float b1 = (w == 0) ? fc2_b[o0+1] : 0.f;
        a0[0]=b0; a0[1]=b0; a0[2]=b0; a0[3]=b0;
        a1[0]=b1; a1[1]=b1; a1[2]=b1; a1[3]=b1;
    }
    const float4* y4 = reinterpret_cast<const float4*>(g_y1);  // [f][b/4]
    int fs = (w * F1) / 32, fe = ((w + 1) * F1) / 32;
    #pragma unroll 4
    for (int f = fs; f < fe; ++f) {
        float4 yv = y4[f*32 + lane];
        float w0 = sw[f], w1 = sw[F1 + f];
        a0[0] = fmaf(w0, yv.x, a0[0]); a1[0] = fmaf(w1, yv.x, a1[0]);
        a0[1] = fmaf(w0, yv.y, a0[1]); a1[1] = fmaf(w1, yv.y, a1[1]);
        a0[2] = fmaf(w0, yv.z, a0[2]); a1[2] = fmaf(w1, yv.z, a1[2]);
        a0[3] = fmaf(w0, yv.w, a0[3]); a1[3] = fmaf(w1, yv.w, a1[3]);
    }
    if (w < 16) {
        #pragma unroll
        for (int u = 0; u < 4; ++u) {
            part[(w*OPB + 0)*B + 4*lane + u] = a0[u];
            part[(w*OPB + 1)*B + 4*lane + u] = a1[u];
        }
    }
    __syncthreads();
    if (w >= 16) {
        #pragma unroll
        for (int u = 0; u < 4; ++u) {
            part[((w-16)*OPB + 0)*B + 4*lane + u] += a0[u];
            part[((w-16)*OPB + 1)*B + 4*lane + u] += a1[u];
        }
    }
    __syncthreads();
    for (int i = tid; i < OPB*B; i += 1024) {
        float s = part[i];
        #pragma unroll
        for (int ks = 1; ks < 16; ++ks) s += part[ks*OPB*B + i];
        int oo = i / B, b = i % B;
        out[b*F2 + o0 + oo] = s;
    }
}

// ---------------------------------------------------------------------------
extern "C" void kernel_launch(void* const* d_in, const int* in_sizes, int n_in,
                              void* d_out, int out_size) {
    const float* births    = (const float*)d_in[0];
    const float* lifetimes = (const float*)d_in[1];
    const int*   mask      = (const int*)  d_in[2];
    const float* centers   = (const float*)d_in[3];
    const float* sharpness = (const float*)d_in[4];
    const float* w1        = (const float*)d_in[5];
    const float* w2        = (const float*)d_in[6];
    const float* l1_w      = (const float*)d_in[7];
    const float* l1_b      = (const float*)d_in[8];
    const float* bn1_g     = (const float*)d_in[9];
    const float* bn1_b     = (const float*)d_in[10];
    const float* l2_w      = (const float*)d_in[11];
    const float* l2_b      = (const float*)d_in[12];
    const float* fc1_w     = (const float*)d_in[13];
    const float* fc1_b     = (const float*)d_in[14];
    const float* bn2_g     = (const float*)d_in[15];
    const float* bn2_b     = (const float*)d_in[16];
    const float* fc2_w     = (const float*)d_in[17];
    const float* fc2_b     = (const float*)d_in[18];
    float* out = (float*)d_out;

    k_slayer<<<V*B/2, 160>>>(births, lifetimes, mask, centers, sharpness);
    k_h     <<<V*8, 256>>>(w1, w2, l1_w, l1_b);
    k_bn    <<<V, 512>>>(bn1_g, bn1_b, l2_w, l2_b);
    k_fc1   <<<F1/FPB, 1024>>>(fc1_w, fc1_b, bn2_g, bn2_b);
    k_fc2   <<<F2/OPB, 1024>>>(fc2_w, fc2_b, out);
}